// round 1
// baseline (speedup 1.0000x reference)
#include <cuda_runtime.h>

#define BB 4
#define DD 128
#define HH 192
#define WW 192
#define HW (HH*WW)          // 36864
#define BHW (BB*HW)         // 147456
#define VOL ((size_t)DD*HW) // 4718592 per batch

// out layout: [x_2d | x_warp | y]
#define OFF_XWARP ((size_t)BHW)
#define OFF_Y     ((size_t)BHW + (size_t)BB*VOL)

// Per-batch 3x3 rotation (row-major) + translation (3): 12 floats
__device__ float g_mat[BB][12];

__global__ void setup_kernel(const float* __restrict__ rot0,
                             const float* __restrict__ rot1,
                             const float* __restrict__ rot2,
                             const float* __restrict__ tr1,
                             const float* __restrict__ tr2,
                             const float* __restrict__ cp) {
    int b = threadIdx.x;
    if (b >= BB) return;
    float az = rot0[b], ay = rot1[b], ax = rot2[b];
    float cz, sz, cy, sy, cx, sx;
    sincosf(az, &sz, &cz);
    sincosf(ay, &sy, &cy);
    sincosf(ax, &sx, &cx);
    // rot = Z @ Y @ X
    float R0 = cz*cy;
    float R1 = -sz*cx + cz*sy*sx;
    float R2 =  sz*sx + cz*sy*cx;
    float R3 = sz*cy;
    float R4 =  cz*cx + sz*sy*sx;
    float R5 = -cz*sx + sz*sy*cx;
    float R6 = -sy;
    float R7 = cy*sx;
    float R8 = cy*cx;
    // trans = (0, trans_1*H, trans_2*W)
    float t0 = 0.0f;
    float t1 = tr1[b] * (float)HH;
    float t2 = tr2[b] * (float)WW;
    float c0 = cp[b*3+0], c1 = cp[b*3+1], c2 = cp[b*3+2];
    // mat = T(+c) @ [R|t] @ T(-c)  ->  R unchanged, t' = t - R*c + c
    float f0 = t0 - (R0*c0 + R1*c1 + R2*c2) + c0;
    float f1 = t1 - (R3*c0 + R4*c1 + R5*c2) + c1;
    float f2 = t2 - (R6*c0 + R7*c1 + R8*c2) + c2;
    g_mat[b][0]=R0; g_mat[b][1]=R1; g_mat[b][2]=R2;
    g_mat[b][3]=R3; g_mat[b][4]=R4; g_mat[b][5]=R5;
    g_mat[b][6]=R6; g_mat[b][7]=R7; g_mat[b][8]=R8;
    g_mat[b][9]=f0; g_mat[b][10]=f1; g_mat[b][11]=f2;
}

__global__ __launch_bounds__(256)
void warp_kernel(const float* __restrict__ x,
                 const float* __restrict__ y,
                 float* __restrict__ out) {
    int idx = blockIdx.x * blockDim.x + threadIdx.x;
    if (idx >= BHW) return;
    int b  = idx / HW;
    int hw = idx - b * HW;
    int h  = hw / WW;
    int w  = hw - h * WW;

    const float* M = g_mat[b];
    float fh = (float)h, fw = (float)w;
    // grid(b,d,h,w) = R * (d,h,w) + t; precompute the h,w-dependent part
    float gz0 = fmaf(M[1], fh, fmaf(M[2], fw, M[9]));
    float gy0 = fmaf(M[4], fh, fmaf(M[5], fw, M[10]));
    float gx0 = fmaf(M[7], fh, fmaf(M[8], fw, M[11]));
    float sz = M[0], sy = M[3], sx = M[6];   // per-d step = R column 0

    const float* __restrict__ vol = x + (size_t)b * VOL;
    float* __restrict__ outw = out + OFF_XWARP + (size_t)b * VOL + (size_t)hw;

    float sum = 0.0f;

    #pragma unroll 4
    for (int d = 0; d < DD; ++d) {
        float fd = (float)d;
        float gz = fmaf(fd, sz, gz0);
        float gy = fmaf(fd, sy, gy0);
        float gx = fmaf(fd, sx, gx0);

        float fz = floorf(gz), fy = floorf(gy), fx = floorf(gx);
        int iz = (int)fz, iy = (int)fy, ix = (int)fx;
        float rz = gz - fz, ry = gy - fy, rx = gx - fx;

        int iz1 = iz + 1, iy1 = iy + 1, ix1 = ix + 1;
        bool vz0 = (iz  >= 0) & (iz  < DD);
        bool vz1 = (iz1 >= 0) & (iz1 < DD);
        bool vy0 = (iy  >= 0) & (iy  < HH);
        bool vy1 = (iy1 >= 0) & (iy1 < HH);
        bool vx0 = (ix  >= 0) & (ix  < WW);
        bool vx1 = (ix1 >= 0) & (ix1 < WW);

        int z0c = min(max(iz , 0), DD-1);
        int z1c = min(max(iz1, 0), DD-1);
        int y0c = min(max(iy , 0), HH-1);
        int y1c = min(max(iy1, 0), HH-1);
        int x0c = min(max(ix , 0), WW-1);
        int x1c = min(max(ix1, 0), WW-1);

        const float* p00 = vol + ((size_t)z0c * HH + y0c) * WW;
        const float* p01 = vol + ((size_t)z0c * HH + y1c) * WW;
        const float* p10 = vol + ((size_t)z1c * HH + y0c) * WW;
        const float* p11 = vol + ((size_t)z1c * HH + y1c) * WW;

        float v000 = (vz0 & vy0 & vx0) ? __ldg(p00 + x0c) : 0.0f;
        float v001 = (vz0 & vy0 & vx1) ? __ldg(p00 + x1c) : 0.0f;
        float v010 = (vz0 & vy1 & vx0) ? __ldg(p01 + x0c) : 0.0f;
        float v011 = (vz0 & vy1 & vx1) ? __ldg(p01 + x1c) : 0.0f;
        float v100 = (vz1 & vy0 & vx0) ? __ldg(p10 + x0c) : 0.0f;
        float v101 = (vz1 & vy0 & vx1) ? __ldg(p10 + x1c) : 0.0f;
        float v110 = (vz1 & vy1 & vx0) ? __ldg(p11 + x0c) : 0.0f;
        float v111 = (vz1 & vy1 & vx1) ? __ldg(p11 + x1c) : 0.0f;

        float wx1f = rx, wx0f = 1.0f - rx;
        float wy1f = ry, wy0f = 1.0f - ry;
        float wz1f = rz, wz0f = 1.0f - rz;

        float a00 = fmaf(v001, wx1f, v000 * wx0f);
        float a01 = fmaf(v011, wx1f, v010 * wx0f);
        float a10 = fmaf(v101, wx1f, v100 * wx0f);
        float a11 = fmaf(v111, wx1f, v110 * wx0f);
        float b0  = fmaf(a01, wy1f, a00 * wy0f);
        float b1  = fmaf(a11, wy1f, a10 * wy0f);
        float val = fmaf(b1,  wz1f, b0  * wz0f);

        outw[(size_t)d * HW] = val;
        sum += val;
    }

    out[idx] = sum * (1.0f / (float)DD);       // x_2d
    out[OFF_Y + idx] = y[idx];                  // y passthrough
}

extern "C" void kernel_launch(void* const* d_in, const int* in_sizes, int n_in,
                              void* d_out, int out_size) {
    const float* x    = (const float*)d_in[0];
    const float* y    = (const float*)d_in[1];
    const float* rot0 = (const float*)d_in[2];
    const float* rot1 = (const float*)d_in[3];
    const float* rot2 = (const float*)d_in[4];
    const float* tr1  = (const float*)d_in[5];
    const float* tr2  = (const float*)d_in[6];
    const float* cp   = (const float*)d_in[7];
    float* out = (float*)d_out;

    setup_kernel<<<1, 32>>>(rot0, rot1, rot2, tr1, tr2, cp);
    warp_kernel<<<(BHW + 255) / 256, 256>>>(x, y, out);
}